// round 4
// baseline (speedup 1.0000x reference)
#include <cuda_runtime.h>

// RK4 step of 2D Burgers-type PDE, (8,2,1024,1024) fp32, periodic wrap,
// 4th-order cross stencils (radius 2).
//
// Stage s computes k_s = f(stage_field), accumulates the RK weighted sum into
// d_out (acc), and writes the next stage field u0 + c*k_s into ping-pong
// __device__ scratch. Stage 4 writes the final result into d_out.

#define IMW 1024
#define IMH 1024
#define HW  (IMW * IMH)
#define NB  8

static __device__ float g_sA[NB * 2 * HW];  // 64 MB
static __device__ float g_sB[NB * 2 * HW];  // 64 MB

__device__ __forceinline__ float4 ld4(const float* __restrict__ p) {
    return *reinterpret_cast<const float4*>(p);
}
__device__ __forceinline__ void st4(float* __restrict__ p, float a, float b, float c, float d) {
    *reinterpret_cast<float4*>(p) = make_float4(a, b, c, d);
}
__device__ __forceinline__ void put4(float* d, float4 v) {
    d[0] = v.x; d[1] = v.y; d[2] = v.z; d[3] = v.w;
}

// STAGE: 1..4
template <int STAGE>
__global__ __launch_bounds__(256) void rk_stage_kernel(
    const float* __restrict__ h,   // original state (8,2,1024,1024)
    float* __restrict__ acc,       // RK accumulator == d_out
    const float* __restrict__ pRe,
    const float* __restrict__ pUA,
    const float* __restrict__ pUB,
    const float* __restrict__ pVA,
    const float* __restrict__ pVB)
{
    const int gid = blockIdx.x * 256 + threadIdx.x;
    const int xq  = gid & 255;          // which group of 4 x's
    const int y   = (gid >> 8) & 1023;
    const int b   = gid >> 18;
    const int x0  = xq << 2;

    const float* sin;
    float*       sout;
    if      (STAGE == 1) { sin = h;    sout = g_sA; }
    else if (STAGE == 2) { sin = g_sA; sout = g_sB; }
    else if (STAGE == 3) { sin = g_sB; sout = g_sA; }
    else                 { sin = g_sA; sout = nullptr; }

    const float nu = 0.001f / pRe[0];
    const float UA = pUA[0], UB = pUB[0], VA = pVA[0], VB = pVB[0];

    const float DX = 0.01f;
    const float inv_dx2 = 1.0f / (DX * DX);
    const float inv_dx  = 1.0f / DX;
    const float c0 = -5.0f, c1 = 4.0f / 3.0f, c2 = -1.0f / 12.0f;  // laplacian taps
    const float d1 = 8.0f / 12.0f, d2 = 1.0f / 12.0f;              // derivative taps

    const int base = b * 2 * HW;
    const float* su = sin + base;
    const float* sv = su + HW;

    const int ym2 = ((y - 2) & 1023) * IMW;
    const int ym1 = ((y - 1) & 1023) * IMW;
    const int yc  = y * IMW;
    const int yp1 = ((y + 1) & 1023) * IMW;
    const int yp2 = ((y + 2) & 1023) * IMW;
    const int xm  = (x0 - 4) & 1023;   // stays 16B-aligned
    const int xp  = (x0 + 4) & 1023;

    // ---- gather u channel (9-point cross, 4-wide) ----
    float u_n2[4], u_n1[4], u_p1[4], u_p2[4], wu[12];
    put4(u_n2, ld4(su + ym2 + x0));
    put4(u_n1, ld4(su + ym1 + x0));
    put4(u_p1, ld4(su + yp1 + x0));
    put4(u_p2, ld4(su + yp2 + x0));
    put4(wu + 0, ld4(su + yc + xm));
    put4(wu + 4, ld4(su + yc + x0));
    put4(wu + 8, ld4(su + yc + xp));

    // ---- gather v channel ----
    float v_n2[4], v_n1[4], v_p1[4], v_p2[4], wv[12];
    put4(v_n2, ld4(sv + ym2 + x0));
    put4(v_n1, ld4(sv + ym1 + x0));
    put4(v_p1, ld4(sv + yp1 + x0));
    put4(v_p2, ld4(sv + yp2 + x0));
    put4(wv + 0, ld4(sv + yc + xm));
    put4(wv + 4, ld4(sv + yc + x0));
    put4(wv + 8, ld4(sv + yc + xp));

    float fu[4], fv[4];
#pragma unroll
    for (int j = 0; j < 4; j++) {
        const float uc = wu[4 + j];
        const float vc = wv[4 + j];

        const float lap_u = (c0 * uc
                           + c1 * (u_n1[j] + u_p1[j] + wu[3 + j] + wu[5 + j])
                           + c2 * (u_n2[j] + u_p2[j] + wu[2 + j] + wu[6 + j])) * inv_dx2;
        const float lap_v = (c0 * vc
                           + c1 * (v_n1[j] + v_p1[j] + wv[3 + j] + wv[5 + j])
                           + c2 * (v_n2[j] + v_p2[j] + wv[2 + j] + wv[6 + j])) * inv_dx2;

        // "u_x" in the reference differentiates along the H axis (rows):
        const float u_x = (d2 * (u_n2[j] - u_p2[j]) + d1 * (u_p1[j] - u_n1[j])) * inv_dx;
        const float v_x = (d2 * (v_n2[j] - v_p2[j]) + d1 * (v_p1[j] - v_n1[j])) * inv_dx;
        // "u_y" differentiates along the W axis (columns):
        const float u_y = (d2 * (wu[2 + j] - wu[6 + j]) + d1 * (wu[5 + j] - wu[3 + j])) * inv_dx;
        const float v_y = (d2 * (wv[2 + j] - wv[6 + j]) + d1 * (wv[5 + j] - wv[3 + j])) * inv_dx;

        fu[j] = nu * lap_u + UA * uc * u_x + UB * vc * u_y;
        fv[j] = nu * lap_v + VA * uc * v_x + VB * vc * v_y;
    }

    const int ou = base + yc + x0;       // offset of u-channel vec
    const int ov = ou + HW;              // offset of v-channel vec

    // original state (center only)
    float hu[4], hv[4];
    if (STAGE == 1) {
#pragma unroll
        for (int j = 0; j < 4; j++) { hu[j] = wu[4 + j]; hv[j] = wv[4 + j]; }
    } else {
        put4(hu, ld4(h + ou));
        put4(hv, ld4(h + ov));
    }

    if (STAGE == 1) {
        // acc = k1 ; stage field = h + (DT/2) k1
        st4(acc + ou, fu[0], fu[1], fu[2], fu[3]);
        st4(acc + ov, fv[0], fv[1], fv[2], fv[3]);
        st4(sout + ou, hu[0] + 0.25f * fu[0], hu[1] + 0.25f * fu[1],
                       hu[2] + 0.25f * fu[2], hu[3] + 0.25f * fu[3]);
        st4(sout + ov, hv[0] + 0.25f * fv[0], hv[1] + 0.25f * fv[1],
                       hv[2] + 0.25f * fv[2], hv[3] + 0.25f * fv[3]);
    } else if (STAGE == 2 || STAGE == 3) {
        float au[4], av[4];
        put4(au, ld4(acc + ou));
        put4(av, ld4(acc + ov));
        // acc += 2 k_s
        st4(acc + ou, au[0] + 2.0f * fu[0], au[1] + 2.0f * fu[1],
                      au[2] + 2.0f * fu[2], au[3] + 2.0f * fu[3]);
        st4(acc + ov, av[0] + 2.0f * fv[0], av[1] + 2.0f * fv[1],
                      av[2] + 2.0f * fv[2], av[3] + 2.0f * fv[3]);
        const float cst = (STAGE == 2) ? 0.25f : 0.5f;  // DT/2 or DT
        st4(sout + ou, hu[0] + cst * fu[0], hu[1] + cst * fu[1],
                       hu[2] + cst * fu[2], hu[3] + cst * fu[3]);
        st4(sout + ov, hv[0] + cst * fv[0], hv[1] + cst * fv[1],
                       hv[2] + cst * fv[2], hv[3] + cst * fv[3]);
    } else {  // STAGE 4: out = h + (DT/6) * (acc + k4)
        float au[4], av[4];
        put4(au, ld4(acc + ou));
        put4(av, ld4(acc + ov));
        const float w = 0.5f / 6.0f;
        st4(acc + ou, hu[0] + w * (au[0] + fu[0]), hu[1] + w * (au[1] + fu[1]),
                      hu[2] + w * (au[2] + fu[2]), hu[3] + w * (au[3] + fu[3]));
        st4(acc + ov, hv[0] + w * (av[0] + fv[0]), hv[1] + w * (av[1] + fv[1]),
                      hv[2] + w * (av[2] + fv[2]), hv[3] + w * (av[3] + fv[3]));
    }
}

extern "C" void kernel_launch(void* const* d_in, const int* in_sizes, int n_in,
                              void* d_out, int out_size)
{
    // Identify inputs robustly: the single large tensor is h; the scalars
    // follow in declaration order Re, UA, UB, VA, VB.
    const float* h = nullptr;
    const float* sc[5] = {nullptr, nullptr, nullptr, nullptr, nullptr};
    int nsc = 0;
    for (int i = 0; i < n_in; i++) {
        if (in_sizes[i] == NB * 2 * HW) {
            h = (const float*)d_in[i];
        } else if (nsc < 5) {
            sc[nsc++] = (const float*)d_in[i];
        }
    }
    const float* Re = sc[0];
    const float* UA = sc[1];
    const float* UB = sc[2];
    const float* VA = sc[3];
    const float* VB = sc[4];

    float* acc = (float*)d_out;

    const int threads = 256;
    const int blocks  = (NB * 2 * HW / 4) / threads / 2;  // = NB*1024 = 8192
    // (each thread covers 4 x-values of one channel-pair site => NB*1024*256 threads)

    rk_stage_kernel<1><<<NB * 1024, threads>>>(h, acc, Re, UA, UB, VA, VB);
    rk_stage_kernel<2><<<NB * 1024, threads>>>(h, acc, Re, UA, UB, VA, VB);
    rk_stage_kernel<3><<<NB * 1024, threads>>>(h, acc, Re, UA, UB, VA, VB);
    rk_stage_kernel<4><<<NB * 1024, threads>>>(h, acc, Re, UA, UB, VA, VB);
    (void)blocks; (void)out_size;
}

// round 5
// speedup vs baseline: 1.6382x; 1.6382x over previous
#include <cuda_runtime.h>

// RK4 step of 2D Burgers-type PDE, (8,2,1024,1024) fp32, periodic wrap,
// 4th-order cross stencils (radius 2).
//
// Two fused kernels:
//   A (stages 1+2): k1 on halo-extended tile -> s1=h+0.25*k1 in SMEM -> k2 from
//      SMEM; writes acc=k1+2*k2 and f2=h+0.25*k2.
//   B (stages 3+4): k3 on extended tile from f2 -> s3=h+0.5*k3 in SMEM -> k4;
//      writes out = h + (DT/6)*(acc + 2*k3 + k4).
// k1/k3 are recovered in phase 2 as (s - h)/c, so no cross-phase register carry.

#define IMW 1024
#define IMH 1024
#define HW  (IMW * IMH)
#define NB  8

#define TX 64
#define TY 32
#define EXW 72                  // TX + 8 (x halo padded to 4 for float4 alignment)
#define EXH 36                  // TY + 4
#define NF4ROW (EXW / 4)        // 18
#define EXF4 (EXH * NF4ROW)     // 648

static __device__ float g_f2[NB * 2 * HW];   // stage-2 field (64 MB)

__device__ __forceinline__ float4 ld4(const float* __restrict__ p) {
    return *reinterpret_cast<const float4*>(p);
}
__device__ __forceinline__ void st4(float* __restrict__ p, float a, float b, float c, float d) {
    *reinterpret_cast<float4*>(p) = make_float4(a, b, c, d);
}
__device__ __forceinline__ void put4(float* d, float4 v) {
    d[0] = v.x; d[1] = v.y; d[2] = v.z; d[3] = v.w;
}

struct Par { float nu, UA, UB, VA, VB; };

__device__ __forceinline__ void rhs4(
    const float un2[4], const float un1[4], const float wu[12],
    const float up1[4], const float up2[4],
    const float vn2[4], const float vn1[4], const float wv[12],
    const float vp1[4], const float vp2[4],
    const Par p, float fu[4], float fv[4])
{
    const float inv_dx2 = 10000.0f;      // 1/DX^2, DX=0.01
    const float inv_dx  = 100.0f;        // 1/DX
    const float c0 = -5.0f, c1 = 4.0f / 3.0f, c2 = -1.0f / 12.0f;
    const float d1 = 8.0f / 12.0f, d2 = 1.0f / 12.0f;
#pragma unroll
    for (int j = 0; j < 4; j++) {
        const float uc = wu[4 + j];
        const float vc = wv[4 + j];
        const float lap_u = (c0 * uc
                           + c1 * (un1[j] + up1[j] + wu[3 + j] + wu[5 + j])
                           + c2 * (un2[j] + up2[j] + wu[2 + j] + wu[6 + j])) * inv_dx2;
        const float lap_v = (c0 * vc
                           + c1 * (vn1[j] + vp1[j] + wv[3 + j] + wv[5 + j])
                           + c2 * (vn2[j] + vp2[j] + wv[2 + j] + wv[6 + j])) * inv_dx2;
        // "u_x" differentiates along the H axis (rows) per reference convention:
        const float u_x = (d2 * (un2[j] - up2[j]) + d1 * (up1[j] - un1[j])) * inv_dx;
        const float v_x = (d2 * (vn2[j] - vp2[j]) + d1 * (vp1[j] - vn1[j])) * inv_dx;
        // "u_y" along W axis (columns):
        const float u_y = (d2 * (wu[2 + j] - wu[6 + j]) + d1 * (wu[5 + j] - wu[3 + j])) * inv_dx;
        const float v_y = (d2 * (wv[2 + j] - wv[6 + j]) + d1 * (wv[5 + j] - wv[3 + j])) * inv_dx;
        fu[j] = p.nu * lap_u + p.UA * uc * u_x + p.UB * vc * u_y;
        fv[j] = p.nu * lap_v + p.VA * uc * v_x + p.VB * vc * v_y;
    }
}

// 9-point cross gather from global with periodic wrap (precomputed row offsets).
__device__ __forceinline__ void gatherG(const float* __restrict__ s,
    int ym2, int ym1, int yc, int yp1, int yp2, int x0, int xm, int xp,
    float n2[4], float n1[4], float w[12], float p1[4], float p2[4])
{
    put4(n2, ld4(s + ym2 + x0));
    put4(n1, ld4(s + ym1 + x0));
    put4(p1, ld4(s + yp1 + x0));
    put4(p2, ld4(s + yp2 + x0));
    put4(w + 0, ld4(s + yc + xm));
    put4(w + 4, ld4(s + yc + x0));
    put4(w + 8, ld4(s + yc + xp));
}

// 9-point cross gather from SMEM tile (halo present, no wrap needed).
__device__ __forceinline__ void gatherS(const float* __restrict__ s, int srow, int sc,
    float n2[4], float n1[4], float w[12], float p1[4], float p2[4])
{
    put4(n2, ld4(s + (srow - 2) * EXW + sc));
    put4(n1, ld4(s + (srow - 1) * EXW + sc));
    put4(p1, ld4(s + (srow + 1) * EXW + sc));
    put4(p2, ld4(s + (srow + 2) * EXW + sc));
    const float* r = s + srow * EXW;
    put4(w + 0, ld4(r + sc - 4));
    put4(w + 4, ld4(r + sc));
    put4(w + 8, ld4(r + sc + 4));
}

// WHICH = 0: stages 1+2.  WHICH = 1: stages 3+4.
template <int WHICH>
__global__ __launch_bounds__(256) void rk_fused_kernel(
    const float* __restrict__ h,    // original state
    float* __restrict__ acc,        // d_out: acc after A, final after B
    float* __restrict__ f2,         // stage-2 field scratch
    const float* __restrict__ pRe,
    const float* __restrict__ pUA,
    const float* __restrict__ pUB,
    const float* __restrict__ pVA,
    const float* __restrict__ pVB)
{
    __shared__ __align__(16) float su[EXH * EXW];
    __shared__ __align__(16) float sv[EXH * EXW];

    const int tid  = threadIdx.x;
    const int x0t  = blockIdx.x * TX;
    const int y0t  = blockIdx.y * TY;
    const int base = blockIdx.z * 2 * HW;

    const Par p = { 0.001f / pRe[0], pUA[0], pUB[0], pVA[0], pVB[0] };

    const float* hu = h + base;
    const float* hv = hu + HW;
    const float* fieldu = (WHICH == 0) ? hu : (g_f2 + base);
    const float* fieldv = fieldu + HW;
    const float  cst = (WHICH == 0) ? 0.25f : 0.5f;   // DT/2 or DT
    const float  icst = (WHICH == 0) ? 4.0f : 2.0f;   // 1/cst

    // ---- phase 1: k on halo-2-extended tile, stage field -> SMEM ----
    for (int e = tid; e < EXF4; e += 256) {
        const int row = e / NF4ROW;
        const int cc  = e - row * NF4ROW;
        const int gy = (y0t + row - 2) & 1023;
        const int gx = (x0t + cc * 4 - 4) & 1023;
        const int ym2 = ((gy - 2) & 1023) * IMW;
        const int ym1 = ((gy - 1) & 1023) * IMW;
        const int yc  = gy * IMW;
        const int yp1 = ((gy + 1) & 1023) * IMW;
        const int yp2 = ((gy + 2) & 1023) * IMW;
        const int xm = (gx - 4) & 1023;
        const int xp = (gx + 4) & 1023;

        float un2[4], un1[4], wu[12], up1[4], up2[4];
        float vn2[4], vn1[4], wv[12], vp1[4], vp2[4];
        gatherG(fieldu, ym2, ym1, yc, yp1, yp2, gx, xm, xp, un2, un1, wu, up1, up2);
        gatherG(fieldv, ym2, ym1, yc, yp1, yp2, gx, xm, xp, vn2, vn1, wv, vp1, vp2);
        float fu[4], fv[4];
        rhs4(un2, un1, wu, up1, up2, vn2, vn1, wv, vp1, vp2, p, fu, fv);

        float hcu[4], hcv[4];
        if (WHICH == 0) {
#pragma unroll
            for (int j = 0; j < 4; j++) { hcu[j] = wu[4 + j]; hcv[j] = wv[4 + j]; }
        } else {
            put4(hcu, ld4(hu + yc + gx));
            put4(hcv, ld4(hv + yc + gx));
        }
        const int so = row * EXW + cc * 4;
#pragma unroll
        for (int j = 0; j < 4; j++) {
            su[so + j] = hcu[j] + cst * fu[j];
            sv[so + j] = hcv[j] + cst * fv[j];
        }
    }
    __syncthreads();

    // ---- phase 2: next k from SMEM on inner tile, write outputs ----
#pragma unroll
    for (int k = 0; k < 2; k++) {
        const int i = tid + k * 256;
        const int irow = i >> 4;          // 16 float4 groups per 64-wide row
        const int icol = i & 15;
        const int srow = irow + 2;
        const int sc   = icol * 4 + 4;

        float un2[4], un1[4], wu[12], up1[4], up2[4];
        float vn2[4], vn1[4], wv[12], vp1[4], vp2[4];
        gatherS(su, srow, sc, un2, un1, wu, up1, up2);
        gatherS(sv, srow, sc, vn2, vn1, wv, vp1, vp2);
        float fu[4], fv[4];                       // k2 (A) or k4 (B)
        rhs4(un2, un1, wu, up1, up2, vn2, vn1, wv, vp1, vp2, p, fu, fv);

        const int gy  = y0t + irow;
        const int gx  = x0t + icol * 4;
        const int off = base + gy * IMW + gx;

        float hu4[4], hv4[4];
        put4(hu4, ld4(h + off));
        put4(hv4, ld4(h + off + HW));

        if (WHICH == 0) {
            // k1 = (s1 - h)/0.25 ; acc = k1 + 2*k2 ; f2 = h + 0.25*k2
            float au[4], av[4], gu[4], gv[4];
#pragma unroll
            for (int j = 0; j < 4; j++) {
                const float k1u = icst * (wu[4 + j] - hu4[j]);
                const float k1v = icst * (wv[4 + j] - hv4[j]);
                au[j] = k1u + 2.0f * fu[j];
                av[j] = k1v + 2.0f * fv[j];
                gu[j] = hu4[j] + 0.25f * fu[j];
                gv[j] = hv4[j] + 0.25f * fv[j];
            }
            st4(acc + off,      au[0], au[1], au[2], au[3]);
            st4(acc + off + HW, av[0], av[1], av[2], av[3]);
            st4(f2  + off,      gu[0], gu[1], gu[2], gu[3]);
            st4(f2  + off + HW, gv[0], gv[1], gv[2], gv[3]);
        } else {
            // k3 = (s3 - h)/0.5 ; out = h + (DT/6)*(acc + 2*k3 + k4)
            float au[4], av[4];
            put4(au, ld4(acc + off));
            put4(av, ld4(acc + off + HW));
            const float w6 = 0.5f / 6.0f;
            float ou[4], ov[4];
#pragma unroll
            for (int j = 0; j < 4; j++) {
                const float k3u = icst * (wu[4 + j] - hu4[j]);
                const float k3v = icst * (wv[4 + j] - hv4[j]);
                ou[j] = hu4[j] + w6 * (au[j] + 2.0f * k3u + fu[j]);
                ov[j] = hv4[j] + w6 * (av[j] + 2.0f * k3v + fv[j]);
            }
            st4(acc + off,      ou[0], ou[1], ou[2], ou[3]);
            st4(acc + off + HW, ov[0], ov[1], ov[2], ov[3]);
        }
    }
}

extern "C" void kernel_launch(void* const* d_in, const int* in_sizes, int n_in,
                              void* d_out, int out_size)
{
    const float* h = nullptr;
    const float* sc[5] = {nullptr, nullptr, nullptr, nullptr, nullptr};
    int nsc = 0;
    for (int i = 0; i < n_in; i++) {
        if (in_sizes[i] == NB * 2 * HW) {
            h = (const float*)d_in[i];
        } else if (nsc < 5) {
            sc[nsc++] = (const float*)d_in[i];
        }
    }
    const float* Re = sc[0];
    const float* UA = sc[1];
    const float* UB = sc[2];
    const float* VA = sc[3];
    const float* VB = sc[4];

    float* acc = (float*)d_out;
    float* f2  = nullptr;
    cudaGetSymbolAddress((void**)&f2, g_f2);

    dim3 grid(IMW / TX, IMH / TY, NB);   // 16 x 32 x 8 = 4096 blocks
    rk_fused_kernel<0><<<grid, 256>>>(h, acc, f2, Re, UA, UB, VA, VB);
    rk_fused_kernel<1><<<grid, 256>>>(h, acc, f2, Re, UA, UB, VA, VB);
    (void)out_size;
}

// round 6
// speedup vs baseline: 1.8031x; 1.1007x over previous
#include <cuda_runtime.h>

// RK4 step of 2D Burgers-type PDE, (8,2,1024,1024) fp32, periodic wrap,
// 4th-order cross stencils (radius 2).
//
// Two fused kernels (stages 1+2 and 3+4), halo recomputation through SMEM.
// R5: 64x64 tiles + vertical register rolling in both phases to cut l1tex
// wavefronts (~45% fewer LDG/LDS than R4).

#define IMW 1024
#define IMH 1024
#define HW  (IMW * IMH)
#define NB  8

#define TX 64
#define TY 64
#define EXW 72                  // TX + 8 (x halo 4 each side, float4-aligned)
#define EXH 68                  // TY + 4
#define NF4 18                  // EXW / 4

static __device__ float g_f2[NB * 2 * HW];   // stage-2 field scratch (64 MB)

__device__ __forceinline__ float4 ld4(const float* __restrict__ p) {
    return *reinterpret_cast<const float4*>(p);
}
__device__ __forceinline__ void st4(float* __restrict__ p, float a, float b, float c, float d) {
    *reinterpret_cast<float4*>(p) = make_float4(a, b, c, d);
}
__device__ __forceinline__ void put4(float* d, float4 v) {
    d[0] = v.x; d[1] = v.y; d[2] = v.z; d[3] = v.w;
}
__device__ __forceinline__ int ro(int gy) { return (gy & 1023) << 10; }

struct Par { float nu, UA, UB, VA, VB; };

// 4-wide RHS. Window rows n2,n1,p1,p2 (center x), w[12] = {left4, center4, right4}.
__device__ __forceinline__ void rhs4(
    const float un2[4], const float un1[4], const float wu[12],
    const float up1[4], const float up2[4],
    const float vn2[4], const float vn1[4], const float wv[12],
    const float vp1[4], const float vp2[4],
    const Par p, float fu[4], float fv[4])
{
    const float inv_dx2 = 10000.0f;
    const float inv_dx  = 100.0f;
    const float c0 = -5.0f, c1 = 4.0f / 3.0f, c2 = -1.0f / 12.0f;
    const float d1 = 8.0f / 12.0f, d2 = 1.0f / 12.0f;
#pragma unroll
    for (int j = 0; j < 4; j++) {
        const float uc = wu[4 + j];
        const float vc = wv[4 + j];
        const float lap_u = (c0 * uc
                           + c1 * (un1[j] + up1[j] + wu[3 + j] + wu[5 + j])
                           + c2 * (un2[j] + up2[j] + wu[2 + j] + wu[6 + j])) * inv_dx2;
        const float lap_v = (c0 * vc
                           + c1 * (vn1[j] + vp1[j] + wv[3 + j] + wv[5 + j])
                           + c2 * (vn2[j] + vp2[j] + wv[2 + j] + wv[6 + j])) * inv_dx2;
        // "u_x" differentiates along H (rows) per reference convention:
        const float u_x = (d2 * (un2[j] - up2[j]) + d1 * (up1[j] - un1[j])) * inv_dx;
        const float v_x = (d2 * (vn2[j] - vp2[j]) + d1 * (vp1[j] - vn1[j])) * inv_dx;
        // "u_y" along W (columns):
        const float u_y = (d2 * (wu[2 + j] - wu[6 + j]) + d1 * (wu[5 + j] - wu[3 + j])) * inv_dx;
        const float v_y = (d2 * (wv[2 + j] - wv[6 + j]) + d1 * (wv[5 + j] - wv[3 + j])) * inv_dx;
        fu[j] = p.nu * lap_u + p.UA * uc * u_x + p.UB * vc * u_y;
        fv[j] = p.nu * lap_v + p.VA * uc * v_x + p.VB * vc * v_y;
    }
}

#define ROT(n2, n1, c, p1, p2) \
    _Pragma("unroll") for (int j = 0; j < 4; j++) { \
        n2[j] = n1[j]; n1[j] = c[j]; c[j] = p1[j]; p1[j] = p2[j]; }

// WHICH = 0: stages 1+2.  WHICH = 1: stages 3+4.
template <int WHICH>
__global__ __launch_bounds__(256, 3) void rk_fused_kernel(
    const float* __restrict__ h,
    float* __restrict__ acc,        // d_out: acc after A, final after B
    float* __restrict__ f2,
    const float* __restrict__ pRe,
    const float* __restrict__ pUA,
    const float* __restrict__ pUB,
    const float* __restrict__ pVA,
    const float* __restrict__ pVB)
{
    __shared__ __align__(16) float su[EXH * EXW];
    __shared__ __align__(16) float sv[EXH * EXW];

    const int tid  = threadIdx.x;
    const int x0t  = blockIdx.x * TX;
    const int y0t  = blockIdx.y * TY;
    const int base = blockIdx.z * 2 * HW;

    const Par p = { 0.001f / pRe[0], pUA[0], pUB[0], pVA[0], pVB[0] };

    const float* hu = h + base;
    const float* hv = hu + HW;
    const float* fieldu = (WHICH == 0) ? hu : (g_f2 + base);
    const float* fieldv = fieldu + HW;
    const float  cst = (WHICH == 0) ? 0.25f : 0.5f;   // DT/2 or DT
    const float  icst = (WHICH == 0) ? 4.0f : 2.0f;

    // ---- phase 1: k on halo-extended tile (rolling y-sweep), s -> SMEM ----
    if (tid < NF4 * 14) {
        const int c4    = tid % NF4;
        const int chunk = tid / NF4;             // 0..13, rows of 5 (last 3)
        const int gx = (x0t + c4 * 4 - 4) & 1023;
        const int xm = (gx - 4) & 1023;
        const int xp = (gx + 4) & 1023;
        const int er0   = chunk * 5;
        const int nrows = (chunk == 13) ? 3 : 5;
        int gy = y0t + er0 - 2;

        float un2[4], un1[4], uc[4], up1[4];
        float vn2[4], vn1[4], vc[4], vp1[4];
        put4(un2, ld4(fieldu + ro(gy - 2) + gx));
        put4(un1, ld4(fieldu + ro(gy - 1) + gx));
        put4(uc,  ld4(fieldu + ro(gy)     + gx));
        put4(up1, ld4(fieldu + ro(gy + 1) + gx));
        put4(vn2, ld4(fieldv + ro(gy - 2) + gx));
        put4(vn1, ld4(fieldv + ro(gy - 1) + gx));
        put4(vc,  ld4(fieldv + ro(gy)     + gx));
        put4(vp1, ld4(fieldv + ro(gy + 1) + gx));

#pragma unroll
        for (int r = 0; r < 5; r++) {
            if (r < nrows) {
                float up2[4], vp2[4], wu[12], wv[12];
                put4(up2, ld4(fieldu + ro(gy + 2) + gx));
                put4(vp2, ld4(fieldv + ro(gy + 2) + gx));
                const int yc = ro(gy);
                put4(wu + 0, ld4(fieldu + yc + xm));
                put4(wu + 8, ld4(fieldu + yc + xp));
                put4(wv + 0, ld4(fieldv + yc + xm));
                put4(wv + 8, ld4(fieldv + yc + xp));
#pragma unroll
                for (int j = 0; j < 4; j++) { wu[4 + j] = uc[j]; wv[4 + j] = vc[j]; }

                float fu[4], fv[4];
                rhs4(un2, un1, wu, up1, up2, vn2, vn1, wv, vp1, vp2, p, fu, fv);

                float hcu[4], hcv[4];
                if (WHICH == 0) {
#pragma unroll
                    for (int j = 0; j < 4; j++) { hcu[j] = uc[j]; hcv[j] = vc[j]; }
                } else {
                    put4(hcu, ld4(hu + yc + gx));
                    put4(hcv, ld4(hv + yc + gx));
                }
                const int so = (er0 + r) * EXW + c4 * 4;
                st4(su + so, hcu[0] + cst * fu[0], hcu[1] + cst * fu[1],
                             hcu[2] + cst * fu[2], hcu[3] + cst * fu[3]);
                st4(sv + so, hcv[0] + cst * fv[0], hcv[1] + cst * fv[1],
                             hcv[2] + cst * fv[2], hcv[3] + cst * fv[3]);

                ROT(un2, un1, uc, up1, up2);
                ROT(vn2, vn1, vc, vp1, vp2);
                gy++;
            }
        }
    }
    __syncthreads();

    // ---- phase 2: next k from SMEM (rolling y-sweep over 4 rows) ----
    {
        const int g  = tid & 15;         // x float4 group within tile
        const int rc = tid >> 4;         // row chunk 0..15
        const int r0 = rc * 4;           // first tile row of this thread
        const int sc = g * 4 + 4;        // smem float col of center

        float un2[4], un1[4], uc[4], up1[4];
        float vn2[4], vn1[4], vc[4], vp1[4];
        put4(un2, ld4(su + (r0 + 0) * EXW + sc));
        put4(un1, ld4(su + (r0 + 1) * EXW + sc));
        put4(uc,  ld4(su + (r0 + 2) * EXW + sc));
        put4(up1, ld4(su + (r0 + 3) * EXW + sc));
        put4(vn2, ld4(sv + (r0 + 0) * EXW + sc));
        put4(vn1, ld4(sv + (r0 + 1) * EXW + sc));
        put4(vc,  ld4(sv + (r0 + 2) * EXW + sc));
        put4(vp1, ld4(sv + (r0 + 3) * EXW + sc));

#pragma unroll
        for (int r = 0; r < 4; r++) {
            float up2[4], vp2[4], wu[12], wv[12];
            put4(up2, ld4(su + (r0 + 4 + r) * EXW + sc));
            put4(vp2, ld4(sv + (r0 + 4 + r) * EXW + sc));
            const float* ru = su + (r0 + 2 + r) * EXW;
            const float* rv = sv + (r0 + 2 + r) * EXW;
            put4(wu + 0, ld4(ru + sc - 4));
            put4(wu + 8, ld4(ru + sc + 4));
            put4(wv + 0, ld4(rv + sc - 4));
            put4(wv + 8, ld4(rv + sc + 4));
#pragma unroll
            for (int j = 0; j < 4; j++) { wu[4 + j] = uc[j]; wv[4 + j] = vc[j]; }

            float fu[4], fv[4];                 // k2 (A) or k4 (B)
            rhs4(un2, un1, wu, up1, up2, vn2, vn1, wv, vp1, vp2, p, fu, fv);

            const int gy  = y0t + r0 + r;
            const int gx  = x0t + g * 4;
            const int off = base + (gy << 10) + gx;

            float hu4[4], hv4[4];
            put4(hu4, ld4(h + off));
            put4(hv4, ld4(h + off + HW));

            if (WHICH == 0) {
                // k1 = (s1 - h)*4 ; acc = k1 + 2*k2 ; f2 = h + 0.25*k2
                float au[4], av[4], gu[4], gv[4];
#pragma unroll
                for (int j = 0; j < 4; j++) {
                    const float k1u = icst * (uc[j] - hu4[j]);
                    const float k1v = icst * (vc[j] - hv4[j]);
                    au[j] = k1u + 2.0f * fu[j];
                    av[j] = k1v + 2.0f * fv[j];
                    gu[j] = hu4[j] + 0.25f * fu[j];
                    gv[j] = hv4[j] + 0.25f * fv[j];
                }
                st4(acc + off,      au[0], au[1], au[2], au[3]);
                st4(acc + off + HW, av[0], av[1], av[2], av[3]);
                st4(f2  + off,      gu[0], gu[1], gu[2], gu[3]);
                st4(f2  + off + HW, gv[0], gv[1], gv[2], gv[3]);
            } else {
                // k3 = (s3 - h)*2 ; out = h + (DT/6)*(acc + 2*k3 + k4)
                float au[4], av[4];
                put4(au, ld4(acc + off));
                put4(av, ld4(acc + off + HW));
                const float w6 = 0.5f / 6.0f;
                float ou[4], ov[4];
#pragma unroll
                for (int j = 0; j < 4; j++) {
                    const float k3u = icst * (uc[j] - hu4[j]);
                    const float k3v = icst * (vc[j] - hv4[j]);
                    ou[j] = hu4[j] + w6 * (au[j] + 2.0f * k3u + fu[j]);
                    ov[j] = hv4[j] + w6 * (av[j] + 2.0f * k3v + fv[j]);
                }
                st4(acc + off,      ou[0], ou[1], ou[2], ou[3]);
                st4(acc + off + HW, ov[0], ov[1], ov[2], ov[3]);
            }

            ROT(un2, un1, uc, up1, up2);
            ROT(vn2, vn1, vc, vp1, vp2);
        }
    }
}

extern "C" void kernel_launch(void* const* d_in, const int* in_sizes, int n_in,
                              void* d_out, int out_size)
{
    const float* h = nullptr;
    const float* sc[5] = {nullptr, nullptr, nullptr, nullptr, nullptr};
    int nsc = 0;
    for (int i = 0; i < n_in; i++) {
        if (in_sizes[i] == NB * 2 * HW) {
            h = (const float*)d_in[i];
        } else if (nsc < 5) {
            sc[nsc++] = (const float*)d_in[i];
        }
    }
    const float* Re = sc[0];
    const float* UA = sc[1];
    const float* UB = sc[2];
    const float* VA = sc[3];
    const float* VB = sc[4];

    float* acc = (float*)d_out;
    float* f2  = nullptr;
    cudaGetSymbolAddress((void**)&f2, g_f2);

    dim3 grid(IMW / TX, IMH / TY, NB);   // 16 x 16 x 8 = 2048 blocks
    rk_fused_kernel<0><<<grid, 256>>>(h, acc, f2, Re, UA, UB, VA, VB);
    rk_fused_kernel<1><<<grid, 256>>>(h, acc, f2, Re, UA, UB, VA, VB);
    (void)out_size;
}